// round 8
// baseline (speedup 1.0000x reference)
#include <cuda_runtime.h>
#include <cuda_fp16.h>
#include <cuda_bf16.h>
#include <cstdint>
#include <math.h>

// ---------------------------------------------------------------------------
// EnhancedSNNCifar on GB300 — tensor-core edition, round 8.
// Layers 2-6: implicit-GEMM conv with mma.sync m16n8k16 (fp16 in, fp32 acc),
// IPB=4 image batching (weight slabs amortized 4x), BN statistics fused into
// the conv epilogue.  Weights split w = hi + lo (exact for binary spikes).
// ---------------------------------------------------------------------------

#define TT 8
#define NB 128

__device__ float  g_Y[33554432];     // conv outputs NHWC fp32
__device__ __half g_SA[33554432];    // spikes ping
__device__ __half g_SB[8388608];     // spikes pong (pooled)
__device__ float  g_H[131072];       // fc1 spikes [T*N,128]
__device__ __half g_WH[294912];      // split weights hi [layer][tap][cin][cout]
__device__ __half g_WL[294912];      // split weights lo
__device__ float  g_WP[262144];      // fc1 weights permuted [k][j]

__device__ double g_sum[128];
__device__ double g_sumsq[128];
__device__ float  g_inv[128];
__device__ float  g_beta[128];

// ---------------------------------------------------------------------------
__device__ __forceinline__ void ldmA(uint32_t* a, const __half* p){
    uint32_t addr = (uint32_t)__cvta_generic_to_shared(p);
    asm volatile("ldmatrix.sync.aligned.m8n8.x4.shared.b16 {%0,%1,%2,%3}, [%4];"
        : "=r"(a[0]), "=r"(a[1]), "=r"(a[2]), "=r"(a[3]) : "r"(addr));
}
__device__ __forceinline__ void ldmB(uint32_t* b, const __half* p){
    uint32_t addr = (uint32_t)__cvta_generic_to_shared(p);
    asm volatile("ldmatrix.sync.aligned.m8n8.x2.trans.shared.b16 {%0,%1}, [%2];"
        : "=r"(b[0]), "=r"(b[1]) : "r"(addr));
}
__device__ __forceinline__ void mma16816(float* d, const uint32_t* a, const uint32_t* b){
    asm volatile("mma.sync.aligned.m16n8k16.row.col.f32.f16.f16.f32 "
        "{%0,%1,%2,%3}, {%4,%5,%6,%7}, {%8,%9}, {%0,%1,%2,%3};"
        : "+f"(d[0]), "+f"(d[1]), "+f"(d[2]), "+f"(d[3])
        : "r"(a[0]), "r"(a[1]), "r"(a[2]), "r"(a[3]), "r"(b[0]), "r"(b[1]));
}

// ---------------------------------------------------------------------------
__global__ void prep_w(const float* __restrict__ w, __half* __restrict__ wh,
                       __half* __restrict__ wl, int CIN, int COUT)
{
    int idx = blockIdx.x*256 + threadIdx.x;
    int tot = COUT*CIN*9;
    if (idx >= tot) return;
    int cout = idx / (CIN*9);
    int r    = idx % (CIN*9);
    int cin  = r / 9;
    int tap  = r % 9;
    float v  = w[idx];
    __half hi = __float2half_rn(v);
    __half lo = __float2half_rn(v - __half2float(hi));
    size_t o = ((size_t)tap*CIN + cin)*COUT + cout;
    wh[o] = hi; wl[o] = lo;
}

__global__ void fc1_perm(const float* __restrict__ w, float* __restrict__ wp)
{
    int idx = blockIdx.x*256 + threadIdx.x;
    if (idx >= 2048*128) return;
    int j = idx % 128;
    int k = idx / 128;
    int c = k % 128;
    int hw = k / 128;
    wp[(size_t)k*128 + j] = w[(size_t)j*2048 + c*16 + hw];
}

// ---------------------------------------------------------------------------
// Implicit-GEMM 3x3 conv, IPB images per CTA, fused BN stats.
// ---------------------------------------------------------------------------
template<int CIN,int COUT,int H,int W,int TR,int TC,int WR,int WC,int IPB>
__device__ __forceinline__
void conv_mma_body(const __half* __restrict__ S, const __half* __restrict__ Wh,
                   const __half* __restrict__ Wl, float* __restrict__ Y)
{
    constexpr int MT    = TR*TC;
    constexpr int CINP  = CIN + 8;
    constexpr int COUTP = COUT + 8;
    constexpr int MW    = MT/WR;
    constexpr int NW    = COUT/WC;
    constexpr int MM    = MW/16;
    constexpr int NN    = NW/8;
    constexpr int SIN   = (TR+2)*(TC+2)*CINP;

    extern __shared__ __half sm[];
    __half* s_in = sm;                         // IPB x [(TR+2)][(TC+2)][CINP]
    __half* s_wh = sm + IPB*SIN;               // [CIN][COUTP]
    __half* s_wl = s_wh + CIN*COUTP;

    __shared__ float s_bsum[128];
    __shared__ float s_bsq[128];

    const int tid  = threadIdx.x;
    const int warp = tid >> 5, lane = tid & 31;
    const int wr   = warp % WR, wc = warp / WR;
    const int m0   = wr * MW;
    const int n0   = wc * NW;
    const int img0 = blockIdx.z * IPB;
    const int r0   = blockIdx.x * TR;

    // ---- load IPB input tiles with halo (zero padded) ----
    {
        constexpr int POS = (TR+2)*(TC+2);
        constexpr int VE  = CIN/8;
        for (int idx = tid; idx < IPB*POS*VE; idx += 256){
            int i = idx / (POS*VE);
            int r = idx % (POS*VE);
            int p = r / VE, v = r % VE;
            int yy = p/(TC+2), xx = p%(TC+2);
            int gy = r0 + yy - 1, gx = xx - 1;
            uint4 val = make_uint4(0,0,0,0);
            if (gy>=0 && gy<H && gx>=0 && gx<W)
                val = *reinterpret_cast<const uint4*>(
                    S + (size_t)(img0+i)*H*W*CIN + ((size_t)gy*W+gx)*CIN + v*8);
            *reinterpret_cast<uint4*>(s_in + i*SIN + p*CINP + v*8) = val;
        }
    }

    float acc[IPB][MM][NN][4];
#pragma unroll
    for (int i=0;i<IPB;i++)
#pragma unroll
        for (int mi=0;mi<MM;mi++)
#pragma unroll
            for (int ni=0;ni<NN;ni++)
#pragma unroll
                for (int q=0;q<4;q++) acc[i][mi][ni][q] = 0.f;

    int aoff[MM];
#pragma unroll
    for (int mi=0;mi<MM;mi++){
        int p  = m0 + mi*16 + (lane & 15);
        int rr = p / TC, cc = p % TC;
        aoff[mi] = (rr*(TC+2) + cc)*CINP + (lane >> 4)*8;
    }
    const int brow = lane & 15;

    for (int tap = 0; tap < 9; tap++){
        __syncthreads();
        {
            const __half* gwh = Wh + (size_t)tap*CIN*COUT;
            const __half* gwl = Wl + (size_t)tap*CIN*COUT;
            constexpr int VW = CIN*COUT/8;
            for (int idx = tid; idx < VW; idx += 256){
                int ci = idx / (COUT/8), v = idx % (COUT/8);
                *reinterpret_cast<uint4*>(s_wh + ci*COUTP + v*8) =
                    *reinterpret_cast<const uint4*>(gwh + ci*COUT + v*8);
                *reinterpret_cast<uint4*>(s_wl + ci*COUTP + v*8) =
                    *reinterpret_cast<const uint4*>(gwl + ci*COUT + v*8);
            }
        }
        __syncthreads();

        const int tapoff = ((tap/3)*(TC+2) + (tap%3))*CINP;

#pragma unroll
        for (int k0 = 0; k0 < CIN; k0 += 16){
            uint32_t bh[NN][2], bl[NN][2];
            const __half* wrh = s_wh + (k0 + brow)*COUTP + n0;
            const __half* wrl = s_wl + (k0 + brow)*COUTP + n0;
#pragma unroll
            for (int ni=0;ni<NN;ni++){
                ldmB(bh[ni], wrh + ni*8);
                ldmB(bl[ni], wrl + ni*8);
            }
#pragma unroll
            for (int i=0;i<IPB;i++){
                uint32_t a[MM][4];
#pragma unroll
                for (int mi=0;mi<MM;mi++)
                    ldmA(a[mi], s_in + i*SIN + tapoff + aoff[mi] + k0);
#pragma unroll
                for (int mi=0;mi<MM;mi++)
#pragma unroll
                    for (int ni=0;ni<NN;ni++){
                        mma16816(acc[i][mi][ni], a[mi], bh[ni]);
                        mma16816(acc[i][mi][ni], a[mi], bl[ni]);
                    }
            }
        }
    }

    // ---- fused BN statistics ----
    if (tid < COUT){ s_bsum[tid] = 0.f; s_bsq[tid] = 0.f; }
    __syncthreads();
#pragma unroll
    for (int ni=0;ni<NN;ni++){
        float se=0.f, so=0.f, qe=0.f, qo=0.f;
#pragma unroll
        for (int i=0;i<IPB;i++)
#pragma unroll
            for (int mi=0;mi<MM;mi++){
                float a0=acc[i][mi][ni][0], a1=acc[i][mi][ni][1];
                float a2=acc[i][mi][ni][2], a3=acc[i][mi][ni][3];
                se += a0+a2; so += a1+a3;
                qe += a0*a0 + a2*a2; qo += a1*a1 + a3*a3;
            }
#pragma unroll
        for (int off=16; off>=4; off>>=1){
            se += __shfl_down_sync(0xffffffffu, se, off);
            so += __shfl_down_sync(0xffffffffu, so, off);
            qe += __shfl_down_sync(0xffffffffu, qe, off);
            qo += __shfl_down_sync(0xffffffffu, qo, off);
        }
        if (lane < 4){
            int cch = n0 + ni*8 + lane*2;
            atomicAdd(&s_bsum[cch],   se);
            atomicAdd(&s_bsum[cch+1], so);
            atomicAdd(&s_bsq[cch],    qe);
            atomicAdd(&s_bsq[cch+1],  qo);
        }
    }
    __syncthreads();
    if (tid < COUT){
        atomicAdd(&g_sum[tid],   (double)s_bsum[tid]);
        atomicAdd(&g_sumsq[tid], (double)s_bsq[tid]);
    }

    // ---- epilogue: NHWC fp32 stores ----
    const int groupid = lane >> 2, tid4 = lane & 3;
#pragma unroll
    for (int i=0;i<IPB;i++){
        float* Yimg = Y + (size_t)(img0+i)*H*W*COUT;
#pragma unroll
        for (int mi=0;mi<MM;mi++){
#pragma unroll
            for (int half_row=0; half_row<2; half_row++){
                int p  = m0 + mi*16 + groupid + half_row*8;
                int rr = p / TC, cc = p % TC;
                float* dst = Yimg + ((size_t)(r0+rr)*W + cc)*COUT + n0;
#pragma unroll
                for (int ni=0;ni<NN;ni++){
                    float2 v;
                    v.x = acc[i][mi][ni][half_row*2 + 0];
                    v.y = acc[i][mi][ni][half_row*2 + 1];
                    *reinterpret_cast<float2*>(dst + ni*8 + tid4*2) = v;
                }
            }
        }
    }
}

// Named wrappers (avoid host template-id expressions — R6 compiler quirk).
__global__ __launch_bounds__(256,1)
void convL2_k(const __half* __restrict__ S, const __half* __restrict__ Wh,
              const __half* __restrict__ Wl, float* __restrict__ Y)
{ conv_mma_body<32,32,32,32,4,32,4,2,4>(S, Wh, Wl, Y); }

__global__ __launch_bounds__(256,1)
void convL3_k(const __half* __restrict__ S, const __half* __restrict__ Wh,
              const __half* __restrict__ Wl, float* __restrict__ Y)
{ conv_mma_body<32,64,16,16,4,16,2,4,4>(S, Wh, Wl, Y); }

__global__ __launch_bounds__(256,1)
void convL4_k(const __half* __restrict__ S, const __half* __restrict__ Wh,
              const __half* __restrict__ Wl, float* __restrict__ Y)
{ conv_mma_body<64,64,16,16,4,16,2,4,4>(S, Wh, Wl, Y); }

__global__ __launch_bounds__(256,1)
void convL5_k(const __half* __restrict__ S, const __half* __restrict__ Wh,
              const __half* __restrict__ Wl, float* __restrict__ Y)
{ conv_mma_body<64,128,8,8,8,8,2,4,4>(S, Wh, Wl, Y); }

__global__ __launch_bounds__(256,1)
void convL6_k(const __half* __restrict__ S, const __half* __restrict__ Wh,
              const __half* __restrict__ Wl, float* __restrict__ Y)
{ conv_mma_body<128,128,8,8,8,8,2,4,4>(S, Wh, Wl, Y); }

// ---------------------------------------------------------------------------
// conv1: fp32 direct conv, NHWC output.
// ---------------------------------------------------------------------------
template<int CIN,int COUT,int H,int W,int TH,int TW,int TOC,int ICC>
__global__ __launch_bounds__(256)
void conv3x3_f32(const float* __restrict__ x, const float* __restrict__ wgt,
                 const float* __restrict__ bias, float* __restrict__ y)
{
    constexpr int PIX    = TH*TW;
    constexpr int GROUPS = 256/PIX;
    constexpr int TOCT   = TOC/GROUPS;
    constexpr int TIH = TH+2, TIW = TW+2;

    __shared__ float s_in[ICC][TIH][TIW];
    __shared__ float s_w[ICC][9][TOC];

    const int tid = threadIdx.x;
    const int pix = tid % PIX;
    const int grp = tid / PIX;
    const int py  = pix / TW;
    const int px  = pix % TW;

    const int tilesX = W/TW;
    const int tx0 = (blockIdx.x % tilesX)*TW - 1;
    const int ty0 = (blockIdx.x / tilesX)*TH - 1;
    const int n   = blockIdx.z;
    const int ocb = blockIdx.y*TOC;
    const int oc_off = grp*TOCT;

    float4 acc[TOCT/4];
#pragma unroll
    for (int j=0;j<TOCT/4;j++){
        acc[j].x = bias[ocb+oc_off+j*4+0];
        acc[j].y = bias[ocb+oc_off+j*4+1];
        acc[j].z = bias[ocb+oc_off+j*4+2];
        acc[j].w = bias[ocb+oc_off+j*4+3];
    }

    const float* xn = x + (size_t)n*CIN*H*W;

    for (int ic0=0; ic0<CIN; ic0+=ICC){
        __syncthreads();
        for (int idx=tid; idx < ICC*TIH*TIW; idx+=256){
            int ic = idx/(TIH*TIW);
            int r  = idx%(TIH*TIW);
            int yy = r/TIW, xx = r%TIW;
            int gy = ty0+yy, gx = tx0+xx;
            float v = 0.f;
            if (gy>=0 && gy<H && gx>=0 && gx<W)
                v = xn[((ic0+ic)*H + gy)*W + gx];
            s_in[ic][yy][xx] = v;
        }
        for (int idx=tid; idx < ICC*9*TOC; idx+=256){
            int ic = idx/(9*TOC);
            int r  = idx%(9*TOC);
            int k  = r/TOC, oc = r%TOC;
            s_w[ic][k][oc] = wgt[((ocb+oc)*CIN + ic0+ic)*9 + k];
        }
        __syncthreads();

        for (int ic=0; ic<ICC; ++ic){
            float in9[9];
#pragma unroll
            for (int k=0;k<9;k++)
                in9[k] = s_in[ic][py + k/3][px + k%3];
#pragma unroll
            for (int j=0;j<TOCT/4;j++){
#pragma unroll
                for (int k=0;k<9;k++){
                    float4 w4 = *reinterpret_cast<const float4*>(&s_w[ic][k][oc_off + j*4]);
                    acc[j].x = fmaf(in9[k], w4.x, acc[j].x);
                    acc[j].y = fmaf(in9[k], w4.y, acc[j].y);
                    acc[j].z = fmaf(in9[k], w4.z, acc[j].z);
                    acc[j].w = fmaf(in9[k], w4.w, acc[j].w);
                }
            }
        }
    }

    const int gy = ty0+1+py, gx = tx0+1+px;
    float* yo = y + ((size_t)(n*H + gy)*W + gx)*COUT + ocb + oc_off;
#pragma unroll
    for (int j=0;j<TOCT/4;j++)
        *reinterpret_cast<float4*>(yo + j*4) = acc[j];
}

// ---------------------------------------------------------------------------
__global__ __launch_bounds__(128) void bn_zero()
{
    int i = threadIdx.x;
    if (i < 128){ g_sum[i] = 0.0; g_sumsq[i] = 0.0; }
}

__global__ __launch_bounds__(256)
void bn_stats_nhwc(const float* __restrict__ y, int C, int E)
{
    __shared__ float ssum[128], ssq[128];
    int tid = threadIdx.x;
    if (tid < C){ ssum[tid]=0.f; ssq[tid]=0.f; }
    __syncthreads();
    int start  = blockIdx.x*256 + tid;
    int stride = gridDim.x*256;
    float s=0.f, s2=0.f;
    for (int i = start; i < E; i += stride){
        float v = y[i];
        s += v; s2 += v*v;
    }
    int c = start % C;
    atomicAdd(&ssum[c], s);
    atomicAdd(&ssq[c],  s2);
    __syncthreads();
    if (tid < C){
        atomicAdd(&g_sum[c],   (double)ssum[c]);
        atomicAdd(&g_sumsq[c], (double)ssq[c]);
    }
}

__global__ __launch_bounds__(128)
void bn_finalize(const float* __restrict__ g, const float* __restrict__ be,
                 int C, double invCount)
{
    int c = threadIdx.x;
    if (c < C){
        double mean = g_sum[c]*invCount;
        double var  = g_sumsq[c]*invCount - mean*mean;
        float inv = g[c] / sqrtf((float)var + 1e-5f);
        g_inv[c]  = inv;
        g_beta[c] = be[c] - (float)mean*inv;
    }
}

// ---------------------------------------------------------------------------
__global__ __launch_bounds__(256)
void lif_bcast(const float* __restrict__ y, __half* __restrict__ s, int C, int E)
{
    int i = blockIdx.x*blockDim.x + threadIdx.x;
    if (i >= E) return;
    int c = i % C;
    float x = fmaf(y[i], g_inv[c], g_beta[c]);
    float v = 0.f;
#pragma unroll
    for (int t=0;t<TT;t++){
        v += (x - v)*0.5f;
        float sp = (v >= 1.f) ? 1.f : 0.f;
        s[(size_t)t*E + i] = __float2half(sp);
        if (v >= 1.f) v = 0.f;
    }
}

__global__ __launch_bounds__(256)
void lif_seq(const float* __restrict__ y, __half* __restrict__ s, int C, int E)
{
    int i = blockIdx.x*blockDim.x + threadIdx.x;
    if (i >= E) return;
    int c = i % C;
    float inv = g_inv[c], be = g_beta[c];
    float v = 0.f;
#pragma unroll
    for (int t=0;t<TT;t++){
        float x = fmaf(y[(size_t)t*E + i], inv, be);
        v += (x - v)*0.5f;
        float sp = (v >= 1.f) ? 1.f : 0.f;
        s[(size_t)t*E + i] = __float2half(sp);
        if (v >= 1.f) v = 0.f;
    }
}

__global__ __launch_bounds__(256)
void lif_pool(const float* __restrict__ y, __half* __restrict__ s,
              int C, int H, int W, int Eo, int Ei)
{
    int j = blockIdx.x*blockDim.x + threadIdx.x;
    if (j >= Eo) return;
    const int Wo = W/2, Ho = H/2;
    int c  = j % C;
    int wo = (j / C) % Wo;
    int ho = (j / (C*Wo)) % Ho;
    int n  = j / (C*Wo*Ho);
    int base = ((n*H + 2*ho)*W + 2*wo)*C + c;
    float inv = g_inv[c], be = g_beta[c];
    float v0=0.f, v1=0.f, v2=0.f, v3=0.f;
#pragma unroll
    for (int t=0;t<TT;t++){
        const float* yt = y + (size_t)t*Ei;
        float x0 = fmaf(yt[base],         inv, be);
        float x1 = fmaf(yt[base+C],       inv, be);
        float x2 = fmaf(yt[base+W*C],     inv, be);
        float x3 = fmaf(yt[base+W*C+C],   inv, be);
        v0 += (x0 - v0)*0.5f;
        v1 += (x1 - v1)*0.5f;
        v2 += (x2 - v2)*0.5f;
        v3 += (x3 - v3)*0.5f;
        float s0 = (v0>=1.f)?1.f:0.f;
        float s1 = (v1>=1.f)?1.f:0.f;
        float s2 = (v2>=1.f)?1.f:0.f;
        float s3 = (v3>=1.f)?1.f:0.f;
        s[(size_t)t*Eo + j] = __float2half(fmaxf(fmaxf(s0,s1), fmaxf(s2,s3)));
        if (v0>=1.f) v0=0.f;
        if (v1>=1.f) v1=0.f;
        if (v2>=1.f) v2=0.f;
        if (v3>=1.f) v3=0.f;
    }
}

// ---------------------------------------------------------------------------
__global__ __launch_bounds__(128)
void fc1_lif(const __half* __restrict__ f, const float* __restrict__ wp,
             const float* __restrict__ b, float* __restrict__ h)
{
    const int n = blockIdx.x;
    const int j = threadIdx.x;
    __shared__ __half fs[TT][2048];

    for (int idx=j; idx<TT*2048/8; idx+=128){
        int t = idx/(2048/8), v = idx%(2048/8);
        *reinterpret_cast<uint4*>(&fs[t][v*8]) =
            *reinterpret_cast<const uint4*>(f + ((size_t)(t*NB+n))*2048 + v*8);
    }
    __syncthreads();

    float acc[TT];
    float bj = b[j];
#pragma unroll
    for (int t=0;t<TT;t++) acc[t] = bj;

    for (int k=0;k<2048;k++){
        float wv = wp[(size_t)k*128 + j];
#pragma unroll
        for (int t=0;t<TT;t++)
            acc[t] = fmaf(__half2float(fs[t][k]), wv, acc[t]);
    }

    float v = 0.f;
#pragma unroll
    for (int t=0;t<TT;t++){
        v += (acc[t] - v)*0.5f;
        float sp = (v >= 1.f) ? 1.f : 0.f;
        h[((size_t)t*NB + n)*128 + j] = sp;
        if (v >= 1.f) v = 0.f;
    }
}

__global__ __launch_bounds__(128)
void fc2_lif_mean(const float* __restrict__ h, const float* __restrict__ w,
                  const float* __restrict__ b, float* __restrict__ out)
{
    const int n = blockIdx.x;
    const int tid = threadIdx.x;
    __shared__ float hs[TT][128];
    for (int idx=tid; idx<TT*128; idx+=128){
        int t = idx/128, k = idx%128;
        hs[t][k] = h[((size_t)t*NB + n)*128 + k];
    }
    __syncthreads();
    if (tid < 10){
        float v = 0.f, sm = 0.f;
        for (int t=0;t<TT;t++){
            float a = b[tid];
            for (int k=0;k<128;k++)
                a = fmaf(hs[t][k], w[tid*128+k], a);
            v += (a - v)*0.5f;
            float sp = (v >= 1.f) ? 1.f : 0.f;
            sm += sp;
            if (v >= 1.f) v = 0.f;
        }
        out[n*10 + tid] = sm*0.125f;
    }
}

// ---------------------------------------------------------------------------
static inline int cdiv(int a, int b){ return (a+b-1)/b; }

#define WOFF_L2 0
#define WOFF_L3 9216
#define WOFF_L4 27648
#define WOFF_L5 64512
#define WOFF_L6 138240

extern "C" void kernel_launch(void* const* d_in, const int* in_sizes, int n_in,
                              void* d_out, int out_size)
{
    const float* x    = (const float*)d_in[0];
    const float* w1   = (const float*)d_in[1];
    const float* b1   = (const float*)d_in[2];
    const float* gm1  = (const float*)d_in[3];
    const float* be1  = (const float*)d_in[4];
    const float* w2   = (const float*)d_in[5];
    const float* gm2  = (const float*)d_in[7];
    const float* be2  = (const float*)d_in[8];
    const float* w3   = (const float*)d_in[9];
    const float* gm3  = (const float*)d_in[11];
    const float* be3  = (const float*)d_in[12];
    const float* w4   = (const float*)d_in[13];
    const float* gm4  = (const float*)d_in[15];
    const float* be4  = (const float*)d_in[16];
    const float* w5   = (const float*)d_in[17];
    const float* gm5  = (const float*)d_in[19];
    const float* be5  = (const float*)d_in[20];
    const float* w6   = (const float*)d_in[21];
    const float* gm6  = (const float*)d_in[23];
    const float* be6  = (const float*)d_in[24];
    const float* fc1w = (const float*)d_in[25];
    const float* fc1b = (const float*)d_in[26];
    const float* fc2w = (const float*)d_in[27];
    const float* fc2b = (const float*)d_in[28];
    float* out = (float*)d_out;

    float *Y, *Hb, *WP;
    __half *SA, *SB, *WH, *WL;
    cudaGetSymbolAddress((void**)&Y,  g_Y);
    cudaGetSymbolAddress((void**)&SA, g_SA);
    cudaGetSymbolAddress((void**)&SB, g_SB);
    cudaGetSymbolAddress((void**)&Hb, g_H);
    cudaGetSymbolAddress((void**)&WH, g_WH);
    cudaGetSymbolAddress((void**)&WL, g_WL);
    cudaGetSymbolAddress((void**)&WP, g_WP);

    const int M  = TT*NB;     // 1024
    const int MZ = M/4;       // 256 image groups (IPB=4)

    cudaFuncSetAttribute(convL2_k, cudaFuncAttributeMaxDynamicSharedMemorySize, 70400);
    cudaFuncSetAttribute(convL3_k, cudaFuncAttributeMaxDynamicSharedMemorySize, 43776);
    cudaFuncSetAttribute(convL4_k, cudaFuncAttributeMaxDynamicSharedMemorySize, 80640);
    cudaFuncSetAttribute(convL5_k, cudaFuncAttributeMaxDynamicSharedMemorySize, 92416);
    cudaFuncSetAttribute(convL6_k, cudaFuncAttributeMaxDynamicSharedMemorySize, 178432);

    // ---- weight prep ----
    prep_w<<<cdiv(32*32*9,256),256>>>(w2, WH+WOFF_L2, WL+WOFF_L2, 32, 32);
    prep_w<<<cdiv(64*32*9,256),256>>>(w3, WH+WOFF_L3, WL+WOFF_L3, 32, 64);
    prep_w<<<cdiv(64*64*9,256),256>>>(w4, WH+WOFF_L4, WL+WOFF_L4, 64, 64);
    prep_w<<<cdiv(128*64*9,256),256>>>(w5, WH+WOFF_L5, WL+WOFF_L5, 64, 128);
    prep_w<<<cdiv(128*128*9,256),256>>>(w6, WH+WOFF_L6, WL+WOFF_L6, 128, 128);
    fc1_perm<<<cdiv(2048*128,256),256>>>(fc1w, WP);

    // ---- Layer 1: fp32 conv (3->32) on N=128, NHWC out ----
    conv3x3_f32<3,32,32,32,16,16,16,3><<<dim3(4,2,NB),256>>>(x, w1, b1, Y);
    bn_zero<<<1,128>>>();
    bn_stats_nhwc<<<512,256>>>(Y, 32, NB*32*32*32);
    bn_finalize<<<1,128>>>(gm1, be1, 32, 1.0/((double)NB*32*32));
    {
        int E = NB*32*32*32;
        lif_bcast<<<cdiv(E,256),256>>>(Y, SA, 32, E);
    }

    // ---- Layer 2 ----
    bn_zero<<<1,128>>>();
    convL2_k<<<dim3(8,1,MZ),256,70400>>>(SA, WH+WOFF_L2, WL+WOFF_L2, Y);
    bn_finalize<<<1,128>>>(gm2, be2, 32, 1.0/((double)M*32*32));
    {
        int Ei = NB*32*32*32, Eo = NB*32*16*16;
        lif_pool<<<cdiv(Eo,256),256>>>(Y, SB, 32, 32, 32, Eo, Ei);
    }

    // ---- Layer 3 ----
    bn_zero<<<1,128>>>();
    convL3_k<<<dim3(4,1,MZ),256,43776>>>(SB, WH+WOFF_L3, WL+WOFF_L3, Y);
    bn_finalize<<<1,128>>>(gm3, be3, 64, 1.0/((double)M*16*16));
    {
        int E = NB*64*16*16;
        lif_seq<<<cdiv(E,256),256>>>(Y, SA, 64, E);
    }

    // ---- Layer 4 ----
    bn_zero<<<1,128>>>();
    convL4_k<<<dim3(4,1,MZ),256,80640>>>(SA, WH+WOFF_L4, WL+WOFF_L4, Y);
    bn_finalize<<<1,128>>>(gm4, be4, 64, 1.0/((double)M*16*16));
    {
        int Ei = NB*64*16*16, Eo = NB*64*8*8;
        lif_pool<<<cdiv(Eo,256),256>>>(Y, SB, 64, 16, 16, Eo, Ei);
    }

    // ---- Layer 5 ----
    bn_zero<<<1,128>>>();
    convL5_k<<<dim3(1,1,MZ),256,92416>>>(SB, WH+WOFF_L5, WL+WOFF_L5, Y);
    bn_finalize<<<1,128>>>(gm5, be5, 128, 1.0/((double)M*8*8));
    {
        int E = NB*128*8*8;
        lif_seq<<<cdiv(E,256),256>>>(Y, SA, 128, E);
    }

    // ---- Layer 6 ----
    bn_zero<<<1,128>>>();
    convL6_k<<<dim3(1,1,MZ),256,178432>>>(SA, WH+WOFF_L6, WL+WOFF_L6, Y);
    bn_finalize<<<1,128>>>(gm6, be6, 128, 1.0/((double)M*8*8));
    {
        int Ei = NB*128*8*8, Eo = NB*128*4*4;
        lif_pool<<<cdiv(Eo,256),256>>>(Y, SB, 128, 8, 8, Eo, Ei);
    }

    // ---- FC head ----
    fc1_lif<<<NB,128>>>(SB, WP, fc1b, Hb);
    fc2_lif_mean<<<NB,128>>>(Hb, fc2w, fc2b, out);
}

// round 10
// speedup vs baseline: 1.1179x; 1.1179x over previous
#include <cuda_runtime.h>
#include <cuda_fp16.h>
#include <cuda_bf16.h>
#include <cstdint>
#include <math.h>

// ---------------------------------------------------------------------------
// EnhancedSNNCifar on GB300 — tensor-core edition, round 9 (resubmit).
// R7 tiling (proven 929us) + BN statistics fused into the conv epilogue
// (removes the bn_stats re-read of Y for layers 2-6).
// ---------------------------------------------------------------------------

#define TT 8
#define NB 128

__device__ float  g_Y[33554432];     // conv outputs NHWC fp32
__device__ __half g_SA[33554432];    // spikes ping
__device__ __half g_SB[8388608];     // spikes pong (pooled)
__device__ float  g_H[131072];       // fc1 spikes [T*N,128]
__device__ __half g_WH[294912];      // split weights hi [layer][tap][cin][cout]
__device__ __half g_WL[294912];      // split weights lo
__device__ float  g_WP[262144];      // fc1 weights permuted [k][j]

__device__ double g_sum[128];
__device__ double g_sumsq[128];
__device__ float  g_inv[128];
__device__ float  g_beta[128];

// ---------------------------------------------------------------------------
__device__ __forceinline__ void ldmA(uint32_t* a, const __half* p){
    uint32_t addr = (uint32_t)__cvta_generic_to_shared(p);
    asm volatile("ldmatrix.sync.aligned.m8n8.x4.shared.b16 {%0,%1,%2,%3}, [%4];"
        : "=r"(a[0]), "=r"(a[1]), "=r"(a[2]), "=r"(a[3]) : "r"(addr));
}
__device__ __forceinline__ void ldmB(uint32_t* b, const __half* p){
    uint32_t addr = (uint32_t)__cvta_generic_to_shared(p);
    asm volatile("ldmatrix.sync.aligned.m8n8.x2.trans.shared.b16 {%0,%1}, [%2];"
        : "=r"(b[0]), "=r"(b[1]) : "r"(addr));
}
__device__ __forceinline__ void mma16816(float* d, const uint32_t* a, const uint32_t* b){
    asm volatile("mma.sync.aligned.m16n8k16.row.col.f32.f16.f16.f32 "
        "{%0,%1,%2,%3}, {%4,%5,%6,%7}, {%8,%9}, {%0,%1,%2,%3};"
        : "+f"(d[0]), "+f"(d[1]), "+f"(d[2]), "+f"(d[3])
        : "r"(a[0]), "r"(a[1]), "r"(a[2]), "r"(a[3]), "r"(b[0]), "r"(b[1]));
}

// ---------------------------------------------------------------------------
__global__ void prep_w(const float* __restrict__ w, __half* __restrict__ wh,
                       __half* __restrict__ wl, int CIN, int COUT)
{
    int idx = blockIdx.x*256 + threadIdx.x;
    int tot = COUT*CIN*9;
    if (idx >= tot) return;
    int cout = idx / (CIN*9);
    int r    = idx % (CIN*9);
    int cin  = r / 9;
    int tap  = r % 9;
    float v  = w[idx];
    __half hi = __float2half_rn(v);
    __half lo = __float2half_rn(v - __half2float(hi));
    size_t o = ((size_t)tap*CIN + cin)*COUT + cout;
    wh[o] = hi; wl[o] = lo;
}

__global__ void fc1_perm(const float* __restrict__ w, float* __restrict__ wp)
{
    int idx = blockIdx.x*256 + threadIdx.x;
    if (idx >= 2048*128) return;
    int j = idx % 128;
    int k = idx / 128;
    int c = k % 128;
    int hw = k / 128;
    wp[(size_t)k*128 + j] = w[(size_t)j*2048 + c*16 + hw];
}

// ---------------------------------------------------------------------------
// Implicit-GEMM 3x3 conv (R7 tiling), fused BN stats in epilogue.
// ---------------------------------------------------------------------------
template<int CIN,int COUT,int H,int W,int TR,int TC,int WR,int WC>
__device__ __forceinline__
void conv_mma_body(const __half* __restrict__ S, const __half* __restrict__ Wh,
                   const __half* __restrict__ Wl, float* __restrict__ Y)
{
    constexpr int MT    = TR*TC;
    constexpr int CINP  = CIN + 8;
    constexpr int COUTP = COUT + 8;
    constexpr int MW    = MT/WR;
    constexpr int NW    = COUT/WC;
    constexpr int MM    = MW/16;
    constexpr int NN    = NW/8;
    constexpr int SIN   = (TR+2)*(TC+2)*CINP;

    extern __shared__ __half sm[];
    __half* s_in = sm;                         // [(TR+2)][(TC+2)][CINP]
    __half* s_wh = sm + SIN;                   // [CIN][COUTP]
    __half* s_wl = s_wh + CIN*COUTP;

    __shared__ float s_bsum[128];
    __shared__ float s_bsq[128];

    const int tid  = threadIdx.x;
    const int warp = tid >> 5, lane = tid & 31;
    const int wr   = warp % WR, wc = warp / WR;
    const int m0   = wr * MW;
    const int n0   = wc * NW;
    const int img  = blockIdx.z;
    const int r0   = blockIdx.x * TR;

    // ---- load input tile with halo (zero padded) ----
    {
        const __half* Simg = S + (size_t)img * H * W * CIN;
        constexpr int POS = (TR+2)*(TC+2);
        constexpr int VE  = CIN/8;
        for (int idx = tid; idx < POS*VE; idx += 256){
            int p = idx / VE, v = idx % VE;
            int yy = p/(TC+2), xx = p%(TC+2);
            int gy = r0 + yy - 1, gx = xx - 1;
            uint4 val = make_uint4(0,0,0,0);
            if (gy>=0 && gy<H && gx>=0 && gx<W)
                val = *reinterpret_cast<const uint4*>(Simg + ((size_t)gy*W+gx)*CIN + v*8);
            *reinterpret_cast<uint4*>(s_in + p*CINP + v*8) = val;
        }
    }

    float acc[MM][NN][4];
#pragma unroll
    for (int mi=0;mi<MM;mi++)
#pragma unroll
        for (int ni=0;ni<NN;ni++)
#pragma unroll
            for (int q=0;q<4;q++) acc[mi][ni][q] = 0.f;

    int aoff[MM];
#pragma unroll
    for (int mi=0;mi<MM;mi++){
        int p  = m0 + mi*16 + (lane & 15);
        int rr = p / TC, cc = p % TC;
        aoff[mi] = (rr*(TC+2) + cc)*CINP + (lane >> 4)*8;
    }
    const int brow = lane & 15;

    for (int tap = 0; tap < 9; tap++){
        __syncthreads();
        {
            const __half* gwh = Wh + (size_t)tap*CIN*COUT;
            const __half* gwl = Wl + (size_t)tap*CIN*COUT;
            constexpr int VW = CIN*COUT/8;
            for (int idx = tid; idx < VW; idx += 256){
                int ci = idx / (COUT/8), v = idx % (COUT/8);
                *reinterpret_cast<uint4*>(s_wh + ci*COUTP + v*8) =
                    *reinterpret_cast<const uint4*>(gwh + ci*COUT + v*8);
                *reinterpret_cast<uint4*>(s_wl + ci*COUTP + v*8) =
                    *reinterpret_cast<const uint4*>(gwl + ci*COUT + v*8);
            }
        }
        __syncthreads();

        const int tapoff = ((tap/3)*(TC+2) + (tap%3))*CINP;

#pragma unroll
        for (int k0 = 0; k0 < CIN; k0 += 16){
            uint32_t a[MM][4];
#pragma unroll
            for (int mi=0;mi<MM;mi++)
                ldmA(a[mi], s_in + tapoff + aoff[mi] + k0);

            uint32_t bh[NN][2], bl[NN][2];
            const __half* wrh = s_wh + (k0 + brow)*COUTP + n0;
            const __half* wrl = s_wl + (k0 + brow)*COUTP + n0;
#pragma unroll
            for (int ni=0;ni<NN;ni++){
                ldmB(bh[ni], wrh + ni*8);
                ldmB(bl[ni], wrl + ni*8);
            }
#pragma unroll
            for (int mi=0;mi<MM;mi++)
#pragma unroll
                for (int ni=0;ni<NN;ni++){
                    mma16816(acc[mi][ni], a[mi], bh[ni]);
                    mma16816(acc[mi][ni], a[mi], bl[ni]);
                }
        }
    }

    // ---- fused BN statistics (per-channel sum / sumsq) ----
    if (tid < COUT){ s_bsum[tid] = 0.f; s_bsq[tid] = 0.f; }
    __syncthreads();
#pragma unroll
    for (int ni=0;ni<NN;ni++){
        float se=0.f, so=0.f, qe=0.f, qo=0.f;
#pragma unroll
        for (int mi=0;mi<MM;mi++){
            float a0=acc[mi][ni][0], a1=acc[mi][ni][1];
            float a2=acc[mi][ni][2], a3=acc[mi][ni][3];
            se += a0+a2; so += a1+a3;
            qe += a0*a0 + a2*a2; qo += a1*a1 + a3*a3;
        }
#pragma unroll
        for (int off=16; off>=4; off>>=1){
            se += __shfl_down_sync(0xffffffffu, se, off);
            so += __shfl_down_sync(0xffffffffu, so, off);
            qe += __shfl_down_sync(0xffffffffu, qe, off);
            qo += __shfl_down_sync(0xffffffffu, qo, off);
        }
        if (lane < 4){
            int cch = n0 + ni*8 + lane*2;
            atomicAdd(&s_bsum[cch],   se);
            atomicAdd(&s_bsum[cch+1], so);
            atomicAdd(&s_bsq[cch],    qe);
            atomicAdd(&s_bsq[cch+1],  qo);
        }
    }
    __syncthreads();
    if (tid < COUT){
        atomicAdd(&g_sum[tid],   (double)s_bsum[tid]);
        atomicAdd(&g_sumsq[tid], (double)s_bsq[tid]);
    }

    // ---- epilogue: NHWC fp32 stores ----
    const int groupid = lane >> 2, tid4 = lane & 3;
    float* Yimg = Y + (size_t)img*H*W*COUT;
#pragma unroll
    for (int mi=0;mi<MM;mi++){
#pragma unroll
        for (int half_row=0; half_row<2; half_row++){
            int p  = m0 + mi*16 + groupid + half_row*8;
            int rr = p / TC, cc = p % TC;
            float* dst = Yimg + ((size_t)(r0+rr)*W + cc)*COUT + n0;
#pragma unroll
            for (int ni=0;ni<NN;ni++){
                float2 v;
                v.x = acc[mi][ni][half_row*2 + 0];
                v.y = acc[mi][ni][half_row*2 + 1];
                *reinterpret_cast<float2*>(dst + ni*8 + tid4*2) = v;
            }
        }
    }
}

// Named wrappers (avoid host template-id expressions — R6 compiler quirk).
__global__ __launch_bounds__(256,1)
void convL2_k(const __half* __restrict__ S, const __half* __restrict__ Wh,
              const __half* __restrict__ Wl, float* __restrict__ Y)
{ conv_mma_body<32,32,32,32,4,32,4,2>(S, Wh, Wl, Y); }

__global__ __launch_bounds__(256,1)
void convL3_k(const __half* __restrict__ S, const __half* __restrict__ Wh,
              const __half* __restrict__ Wl, float* __restrict__ Y)
{ conv_mma_body<32,64,16,16,8,16,4,2>(S, Wh, Wl, Y); }

__global__ __launch_bounds__(256,1)
void convL4_k(const __half* __restrict__ S, const __half* __restrict__ Wh,
              const __half* __restrict__ Wl, float* __restrict__ Y)
{ conv_mma_body<64,64,16,16,8,16,4,2>(S, Wh, Wl, Y); }

__global__ __launch_bounds__(256,1)
void convL5_k(const __half* __restrict__ S, const __half* __restrict__ Wh,
              const __half* __restrict__ Wl, float* __restrict__ Y)
{ conv_mma_body<64,128,8,8,8,8,2,4>(S, Wh, Wl, Y); }

__global__ __launch_bounds__(256,1)
void convL6_k(const __half* __restrict__ S, const __half* __restrict__ Wh,
              const __half* __restrict__ Wl, float* __restrict__ Y)
{ conv_mma_body<128,128,8,8,8,8,2,4>(S, Wh, Wl, Y); }

// ---------------------------------------------------------------------------
// conv1: fp32 direct conv, NHWC output.
// ---------------------------------------------------------------------------
template<int CIN,int COUT,int H,int W,int TH,int TW,int TOC,int ICC>
__global__ __launch_bounds__(256)
void conv3x3_f32(const float* __restrict__ x, const float* __restrict__ wgt,
                 const float* __restrict__ bias, float* __restrict__ y)
{
    constexpr int PIX    = TH*TW;
    constexpr int GROUPS = 256/PIX;
    constexpr int TOCT   = TOC/GROUPS;
    constexpr int TIH = TH+2, TIW = TW+2;

    __shared__ float s_in[ICC][TIH][TIW];
    __shared__ float s_w[ICC][9][TOC];

    const int tid = threadIdx.x;
    const int pix = tid % PIX;
    const int grp = tid / PIX;
    const int py  = pix / TW;
    const int px  = pix % TW;

    const int tilesX = W/TW;
    const int tx0 = (blockIdx.x % tilesX)*TW - 1;
    const int ty0 = (blockIdx.x / tilesX)*TH - 1;
    const int n   = blockIdx.z;
    const int ocb = blockIdx.y*TOC;
    const int oc_off = grp*TOCT;

    float4 acc[TOCT/4];
#pragma unroll
    for (int j=0;j<TOCT/4;j++){
        acc[j].x = bias[ocb+oc_off+j*4+0];
        acc[j].y = bias[ocb+oc_off+j*4+1];
        acc[j].z = bias[ocb+oc_off+j*4+2];
        acc[j].w = bias[ocb+oc_off+j*4+3];
    }

    const float* xn = x + (size_t)n*CIN*H*W;

    for (int ic0=0; ic0<CIN; ic0+=ICC){
        __syncthreads();
        for (int idx=tid; idx < ICC*TIH*TIW; idx+=256){
            int ic = idx/(TIH*TIW);
            int r  = idx%(TIH*TIW);
            int yy = r/TIW, xx = r%TIW;
            int gy = ty0+yy, gx = tx0+xx;
            float v = 0.f;
            if (gy>=0 && gy<H && gx>=0 && gx<W)
                v = xn[((ic0+ic)*H + gy)*W + gx];
            s_in[ic][yy][xx] = v;
        }
        for (int idx=tid; idx < ICC*9*TOC; idx+=256){
            int ic = idx/(9*TOC);
            int r  = idx%(9*TOC);
            int k  = r/TOC, oc = r%TOC;
            s_w[ic][k][oc] = wgt[((ocb+oc)*CIN + ic0+ic)*9 + k];
        }
        __syncthreads();

        for (int ic=0; ic<ICC; ++ic){
            float in9[9];
#pragma unroll
            for (int k=0;k<9;k++)
                in9[k] = s_in[ic][py + k/3][px + k%3];
#pragma unroll
            for (int j=0;j<TOCT/4;j++){
#pragma unroll
                for (int k=0;k<9;k++){
                    float4 w4 = *reinterpret_cast<const float4*>(&s_w[ic][k][oc_off + j*4]);
                    acc[j].x = fmaf(in9[k], w4.x, acc[j].x);
                    acc[j].y = fmaf(in9[k], w4.y, acc[j].y);
                    acc[j].z = fmaf(in9[k], w4.z, acc[j].z);
                    acc[j].w = fmaf(in9[k], w4.w, acc[j].w);
                }
            }
        }
    }

    const int gy = ty0+1+py, gx = tx0+1+px;
    float* yo = y + ((size_t)(n*H + gy)*W + gx)*COUT + ocb + oc_off;
#pragma unroll
    for (int j=0;j<TOCT/4;j++)
        *reinterpret_cast<float4*>(yo + j*4) = acc[j];
}

// ---------------------------------------------------------------------------
__global__ __launch_bounds__(128) void bn_zero()
{
    int i = threadIdx.x;
    if (i < 128){ g_sum[i] = 0.0; g_sumsq[i] = 0.0; }
}

__global__ __launch_bounds__(256)
void bn_stats_nhwc(const float* __restrict__ y, int C, int E)
{
    __shared__ float ssum[128], ssq[128];
    int tid = threadIdx.x;
    if (tid < C){ ssum[tid]=0.f; ssq[tid]=0.f; }
    __syncthreads();
    int start  = blockIdx.x*256 + tid;
    int stride = gridDim.x*256;
    float s=0.f, s2=0.f;
    for (int i = start; i < E; i += stride){
        float v = y[i];
        s += v; s2 += v*v;
    }
    int c = start % C;
    atomicAdd(&ssum[c], s);
    atomicAdd(&ssq[c],  s2);
    __syncthreads();
    if (tid < C){
        atomicAdd(&g_sum[c],   (double)ssum[c]);
        atomicAdd(&g_sumsq[c], (double)ssq[c]);
    }
}

__global__ __launch_bounds__(128)
void bn_finalize(const float* __restrict__ g, const float* __restrict__ be,
                 int C, double invCount)
{
    int c = threadIdx.x;
    if (c < C){
        double mean = g_sum[c]*invCount;
        double var  = g_sumsq[c]*invCount - mean*mean;
        float inv = g[c] / sqrtf((float)var + 1e-5f);
        g_inv[c]  = inv;
        g_beta[c] = be[c] - (float)mean*inv;
    }
}

// ---------------------------------------------------------------------------
__global__ __launch_bounds__(256)
void lif_bcast(const float* __restrict__ y, __half* __restrict__ s, int C, int E)
{
    int i = blockIdx.x*blockDim.x + threadIdx.x;
    if (i >= E) return;
    int c = i % C;
    float x = fmaf(y[i], g_inv[c], g_beta[c]);
    float v = 0.f;
#pragma unroll
    for (int t=0;t<TT;t++){
        v += (x - v)*0.5f;
        float sp = (v >= 1.f) ? 1.f : 0.f;
        s[(size_t)t*E + i] = __float2half(sp);
        if (v >= 1.f) v = 0.f;
    }
}

__global__ __launch_bounds__(256)
void lif_seq(const float* __restrict__ y, __half* __restrict__ s, int C, int E)
{
    int i = blockIdx.x*blockDim.x + threadIdx.x;
    if (i >= E) return;
    int c = i % C;
    float inv = g_inv[c], be = g_beta[c];
    float v = 0.f;
#pragma unroll
    for (int t=0;t<TT;t++){
        float x = fmaf(y[(size_t)t*E + i], inv, be);
        v += (x - v)*0.5f;
        float sp = (v >= 1.f) ? 1.f : 0.f;
        s[(size_t)t*E + i] = __float2half(sp);
        if (v >= 1.f) v = 0.f;
    }
}

__global__ __launch_bounds__(256)
void lif_pool(const float* __restrict__ y, __half* __restrict__ s,
              int C, int H, int W, int Eo, int Ei)
{
    int j = blockIdx.x*blockDim.x + threadIdx.x;
    if (j >= Eo) return;
    const int Wo = W/2, Ho = H/2;
    int c  = j % C;
    int wo = (j / C) % Wo;
    int ho = (j / (C*Wo)) % Ho;
    int n  = j / (C*Wo*Ho);
    int base = ((n*H + 2*ho)*W + 2*wo)*C + c;
    float inv = g_inv[c], be = g_beta[c];
    float v0=0.f, v1=0.f, v2=0.f, v3=0.f;
#pragma unroll
    for (int t=0;t<TT;t++){
        const float* yt = y + (size_t)t*Ei;
        float x0 = fmaf(yt[base],         inv, be);
        float x1 = fmaf(yt[base+C],       inv, be);
        float x2 = fmaf(yt[base+W*C],     inv, be);
        float x3 = fmaf(yt[base+W*C+C],   inv, be);
        v0 += (x0 - v0)*0.5f;
        v1 += (x1 - v1)*0.5f;
        v2 += (x2 - v2)*0.5f;
        v3 += (x3 - v3)*0.5f;
        float s0 = (v0>=1.f)?1.f:0.f;
        float s1 = (v1>=1.f)?1.f:0.f;
        float s2 = (v2>=1.f)?1.f:0.f;
        float s3 = (v3>=1.f)?1.f:0.f;
        s[(size_t)t*Eo + j] = __float2half(fmaxf(fmaxf(s0,s1), fmaxf(s2,s3)));
        if (v0>=1.f) v0=0.f;
        if (v1>=1.f) v1=0.f;
        if (v2>=1.f) v2=0.f;
        if (v3>=1.f) v3=0.f;
    }
}

// ---------------------------------------------------------------------------
__global__ __launch_bounds__(128)
void fc1_lif(const __half* __restrict__ f, const float* __restrict__ wp,
             const float* __restrict__ b, float* __restrict__ h)
{
    const int n = blockIdx.x;
    const int j = threadIdx.x;
    __shared__ __half fs[TT][2048];

    for (int idx=j; idx<TT*2048/8; idx+=128){
        int t = idx/(2048/8), v = idx%(2048/8);
        *reinterpret_cast<uint4*>(&fs[t][v*8]) =
            *reinterpret_cast<const uint4*>(f + ((size_t)(t*NB+n))*2048 + v*8);
    }
    __syncthreads();

    float acc[TT];
    float bj = b[j];
#pragma unroll
    for (int t=0;t<TT;t++) acc[t] = bj;

    for (int k=0;k<2048;k++){
        float wv = wp[(size_t)k*128 + j];
#pragma unroll
        for (int t=0;t<TT;t++)
            acc[t] = fmaf(__half2float(fs[t][k]), wv, acc[t]);
    }

    float v = 0.f;
#pragma unroll
    for (int t=0;t<TT;t++){
        v += (acc[t] - v)*0.5f;
        float sp = (v >= 1.f) ? 1.f : 0.f;
        h[((size_t)t*NB + n)*128 + j] = sp;
        if (v >= 1.f) v = 0.f;
    }
}

__global__ __launch_bounds__(128)
void fc2_lif_mean(const float* __restrict__ h, const float* __restrict__ w,
                  const float* __restrict__ b, float* __restrict__ out)
{
    const int n = blockIdx.x;
    const int tid = threadIdx.x;
    __shared__ float hs[TT][128];
    for (int idx=tid; idx<TT*128; idx+=128){
        int t = idx/128, k = idx%128;
        hs[t][k] = h[((size_t)t*NB + n)*128 + k];
    }
    __syncthreads();
    if (tid < 10){
        float v = 0.f, sm = 0.f;
        for (int t=0;t<TT;t++){
            float a = b[tid];
            for (int k=0;k<128;k++)
                a = fmaf(hs[t][k], w[tid*128+k], a);
            v += (a - v)*0.5f;
            float sp = (v >= 1.f) ? 1.f : 0.f;
            sm += sp;
            if (v >= 1.f) v = 0.f;
        }
        out[n*10 + tid] = sm*0.125f;
    }
}

// ---------------------------------------------------------------------------
static inline int cdiv(int a, int b){ return (a+b-1)/b; }

#define WOFF_L2 0
#define WOFF_L3 9216
#define WOFF_L4 27648
#define WOFF_L5 64512
#define WOFF_L6 138240

extern "C" void kernel_launch(void* const* d_in, const int* in_sizes, int n_in,
                              void* d_out, int out_size)
{
    const float* x    = (const float*)d_in[0];
    const float* w1   = (const float*)d_in[1];
    const float* b1   = (const float*)d_in[2];
    const float* gm1  = (const float*)d_in[3];
    const float* be1  = (const float*)d_in[4];
    const float* w2   = (const float*)d_in[5];
    const float* gm2  = (const float*)d_in[7];
    const float* be2  = (const float*)d_in[8];
    const float* w3   = (const float*)d_in[9];
    const float* gm3  = (const float*)d_in[11];
    const float* be3  = (const float*)d_in[12];
    const float* w4   = (const float*)d_in[13];
    const float* gm4  = (const float*)d_in[15];
    const float* be4  = (const float*)d_in[16];
    const float* w5   = (const float*)d_in[17];
    const float* gm5  = (const float*)d_in[19];
    const float* be5  = (const float*)d_in[20];
    const float* w6   = (const float*)d_in[21];
    const float* gm6  = (const float*)d_in[23];
    const float* be6  = (const float*)d_in[24];
    const float* fc1w = (const float*)d_in[25];
    const float* fc1b = (const float*)d_in[26];
    const float* fc2w = (const float*)d_in[27];
    const float* fc2b = (const float*)d_in[28];
    float* out = (float*)d_out;

    float *Y, *Hb, *WP;
    __half *SA, *SB, *WH, *WL;
    cudaGetSymbolAddress((void**)&Y,  g_Y);
    cudaGetSymbolAddress((void**)&SA, g_SA);
    cudaGetSymbolAddress((void**)&SB, g_SB);
    cudaGetSymbolAddress((void**)&Hb, g_H);
    cudaGetSymbolAddress((void**)&WH, g_WH);
    cudaGetSymbolAddress((void**)&WL, g_WL);
    cudaGetSymbolAddress((void**)&WP, g_WP);

    const int M = TT*NB;   // 1024

    cudaFuncSetAttribute(convL2_k, cudaFuncAttributeMaxDynamicSharedMemorySize, 21440);
    cudaFuncSetAttribute(convL3_k, cudaFuncAttributeMaxDynamicSharedMemorySize, 23616);
    cudaFuncSetAttribute(convL4_k, cudaFuncAttributeMaxDynamicSharedMemorySize, 44352);
    cudaFuncSetAttribute(convL5_k, cudaFuncAttributeMaxDynamicSharedMemorySize, 49216);
    cudaFuncSetAttribute(convL6_k, cudaFuncAttributeMaxDynamicSharedMemorySize, 96832);

    // ---- weight prep ----
    prep_w<<<cdiv(32*32*9,256),256>>>(w2, WH+WOFF_L2, WL+WOFF_L2, 32, 32);
    prep_w<<<cdiv(64*32*9,256),256>>>(w3, WH+WOFF_L3, WL+WOFF_L3, 32, 64);
    prep_w<<<cdiv(64*64*9,256),256>>>(w4, WH+WOFF_L4, WL+WOFF_L4, 64, 64);
    prep_w<<<cdiv(128*64*9,256),256>>>(w5, WH+WOFF_L5, WL+WOFF_L5, 64, 128);
    prep_w<<<cdiv(128*128*9,256),256>>>(w6, WH+WOFF_L6, WL+WOFF_L6, 128, 128);
    fc1_perm<<<cdiv(2048*128,256),256>>>(fc1w, WP);

    // ---- Layer 1: fp32 conv (3->32) on N=128, NHWC out ----
    conv3x3_f32<3,32,32,32,16,16,16,3><<<dim3(4,2,NB),256>>>(x, w1, b1, Y);
    bn_zero<<<1,128>>>();
    bn_stats_nhwc<<<512,256>>>(Y, 32, NB*32*32*32);
    bn_finalize<<<1,128>>>(gm1, be1, 32, 1.0/((double)NB*32*32));
    {
        int E = NB*32*32*32;
        lif_bcast<<<cdiv(E,256),256>>>(Y, SA, 32, E);
    }

    // ---- Layer 2 (fused BN stats in conv) ----
    bn_zero<<<1,128>>>();
    convL2_k<<<dim3(8,1,M),256,21440>>>(SA, WH+WOFF_L2, WL+WOFF_L2, Y);
    bn_finalize<<<1,128>>>(gm2, be2, 32, 1.0/((double)M*32*32));
    {
        int Ei = NB*32*32*32, Eo = NB*32*16*16;
        lif_pool<<<cdiv(Eo,256),256>>>(Y, SB, 32, 32, 32, Eo, Ei);
    }

    // ---- Layer 3 ----
    bn_zero<<<1,128>>>();
    convL3_k<<<dim3(2,1,M),256,23616>>>(SB, WH+WOFF_L3, WL+WOFF_L3, Y);
    bn_finalize<<<1,128>>>(gm3, be3, 64, 1.0/((double)M*16*16));
    {
        int E = NB*64*16*16;
        lif_seq<<<cdiv(E,256),256>>>(Y, SA, 64, E);
    }

    // ---- Layer 4 ----
    bn_zero<<<1,128>>>();
    convL4_k<<<dim3(2,1,M),256,44352>>>(SA, WH+WOFF_L4, WL+WOFF_L4, Y);
    bn_finalize<<<1,128>>>(gm4, be4, 64, 1.0/((double)M*16*16));
    {
        int Ei = NB*64*16*16, Eo = NB*64*8*8;
        lif_pool<<<cdiv(Eo,256),256>>>(Y, SB, 64, 16, 16, Eo, Ei);
    }

    // ---- Layer 5 ----
    bn_zero<<<1,128>>>();
    convL5_k<<<dim3(1,1,M),256,49216>>>(SB, WH+WOFF_L5, WL+WOFF_L5, Y);
    bn_finalize<<<1,128>>>(gm5, be5, 128, 1.0/((double)M*8*8));
    {
        int E = NB*128*8*8;
        lif_seq<<<cdiv(E,256),256>>>(Y, SA, 128, E);
    }

    // ---- Layer 6 ----
    bn_zero<<<1,128>>>();
    convL6_k<<<dim3(1,1,M),256,96832>>>(SA, WH+WOFF_L6, WL+WOFF_L6, Y);
    bn_finalize<<<1,128>>>(gm6, be6, 128, 1.0/((double)M*8*8));
    {
        int Ei = NB*128*8*8, Eo = NB*128*4*4;
        lif_pool<<<cdiv(Eo,256),256>>>(Y, SB, 128, 8, 8, Eo, Ei);
    }

    // ---- FC head ----
    fc1_lif<<<NB,128>>>(SB, WP, fc1b, Hb);
    fc2_lif_mean<<<NB,128>>>(Hb, fc2w, fc2b, out);
}